// round 14
// baseline (speedup 1.0000x reference)
#include <cuda_runtime.h>
#include <cstdint>

// ---------------- scratch (device globals; no allocation allowed) -----------
__device__ float g_qk[8388608];    // [H][8192][128]  q(0:64) | k(64:128)
__device__ float g_v [33554432];   // [H][8192][512]
__device__ float g_at[33554432];   // [8192][4096] concat heads
__device__ float g_mha[4194304];
__device__ float g_h [4194304];
__device__ float g_f1[16777216];   // [8192][2048]
__device__ float g_f2[4194304];
// tf32-rounded copies of raw inputs
__device__ float g_xr [4194304];
__device__ float g_qkw[524288];    // [8][512][128] concat qw|kw rounded
__device__ float g_vwr[2097152];
__device__ float g_lwr[2097152];
__device__ float g_w1r[1048576];
__device__ float g_w2r[1048576];

// ---- kernel 1: 128x128 tile, 2-stage, 2 CTA/SM ----
#define BM 128
#define BN 128
#define ASTRF   36
#define BSTRF_KM 136
#define A_BYTES 18432
#define STAGE   36864
#define SMEM_BYTES 73728

// ---- kernel 3: 64x256 tile, 2-stage, 2 CTA/SM ----
#define A3_BYTES 9216       // 64*36*4
#define B3STR_KM 264
#define STAGE3   43008      // A + B (32*264*4 = 33792)
#define SMEM3    86016

// ---- flash attention smem layout (floats) ----
#define FQ   0        // Q  [128][68]
#define FK   8704     // K  [64][68]
#define FE   13056    // E  [128][68]
#define FV0  21760    // V chunk buf0 [64][136]
#define FV1  30464    // V chunk buf1 [64][136]
#define FRS  39168    // row-sum partials [128][4]
#define FINV 39680    // inv row sums [128]
#define FLASH_SMEM 159232

__device__ __forceinline__ void cp16(uint32_t dst, const void* src) {
    asm volatile("cp.async.cg.shared.global [%0], [%1], 16;" :: "r"(dst), "l"(src));
}
__device__ __forceinline__ void cp16z(uint32_t dst, const void* src) {
    asm volatile("cp.async.cg.shared.global [%0], [%1], 16, %2;"
                 :: "r"(dst), "l"(src), "r"(0));
}
__device__ __forceinline__ float rnd_tf32(float f) {
    uint32_t r;
    asm("cvt.rna.tf32.f32 %0, %1;" : "=r"(r) : "f"(f));
    return __uint_as_float(r);
}
__device__ __forceinline__ void mma_tf32(float* c, const uint32_t* a, const uint32_t* b) {
    asm volatile(
        "mma.sync.aligned.m16n8k8.row.col.f32.tf32.tf32.f32 "
        "{%0,%1,%2,%3},{%4,%5,%6,%7},{%8,%9},{%0,%1,%2,%3};"
        : "+f"(c[0]), "+f"(c[1]), "+f"(c[2]), "+f"(c[3])
        : "r"(a[0]), "r"(a[1]), "r"(a[2]), "r"(a[3]), "r"(b[0]), "r"(b[1]));
}

// ============ kernel 1: 128x128 (QK projection, N=128) ======================
template<bool TB>
__global__ __launch_bounds__(256, 2)
void tf32_gemm(const float* __restrict__ A, const float* __restrict__ B,
               float* __restrict__ C, int M, int N, int K,
               int lda, int ldb, int ldc,
               long long sA, long long sB,
               int zdiv, long long sC1, long long sC2,
               float alpha, const float* __restrict__ bias, int relu, int roundOut)
{
    extern __shared__ __align__(16) char dsm[];
    const uint32_t sBase = (uint32_t)__cvta_generic_to_shared(dsm);

    const int bz = blockIdx.z;
    A += (long long)bz * sA;
    B += (long long)bz * sB;
    const long long cOff = (long long)(bz / zdiv) * sC1 + (long long)(bz % zdiv) * sC2;

    const int mBase = blockIdx.y * BM;
    const int nBase = blockIdx.x * BN;
    const int tid   = threadIdx.x;
    const int lane  = tid & 31;
    const int warp  = tid >> 5;
    const int wm    = warp >> 2;
    const int wn    = warp & 3;
    const int g     = lane >> 2;
    const int tg    = lane & 3;

    float acc[4][4][4];
    #pragma unroll
    for (int i = 0; i < 4; i++)
        #pragma unroll
        for (int j = 0; j < 4; j++)
            #pragma unroll
            for (int e = 0; e < 4; e++) acc[i][j][e] = 0.0f;

    const int nk = K >> 5;

    auto load_tile = [&](int kt, int buf) {
        const int k0 = kt << 5;
        const uint32_t sb = sBase + buf * STAGE;
        #pragma unroll
        for (int it = 0; it < 4; it++) {
            int idx = tid + it * 256;
            int r = idx >> 3, c = idx & 7;
            cp16(sb + r * 144 + c * 16,
                 A + (long long)(mBase + r) * lda + k0 + c * 4);
        }
        if (TB) {
            #pragma unroll
            for (int it = 0; it < 4; it++) {
                int idx = tid + it * 256;
                int r = idx >> 3, c = idx & 7;
                int gn = nBase + r;
                uint32_t dst = sb + A_BYTES + r * 144 + c * 16;
                if (gn < N) cp16(dst, B + (long long)gn * ldb + k0 + c * 4);
                else        cp16z(dst, B);
            }
        } else {
            #pragma unroll
            for (int it = 0; it < 4; it++) {
                int idx = tid + it * 256;
                int r = idx >> 5, cc = idx & 31;
                int gn = nBase + cc * 4;
                uint32_t dst = sb + A_BYTES + r * 544 + cc * 16;
                if (gn < N) cp16(dst, B + (long long)(k0 + r) * ldb + gn);
                else        cp16z(dst, B);
            }
        }
        asm volatile("cp.async.commit_group;" ::: "memory");
    };

    load_tile(0, 0);

    for (int kt = 0; kt < nk; kt++) {
        if (kt + 1 < nk) {
            load_tile(kt + 1, (kt + 1) & 1);
            asm volatile("cp.async.wait_group 1;" ::: "memory");
        } else {
            asm volatile("cp.async.wait_group 0;" ::: "memory");
        }
        __syncthreads();

        const int buf = kt & 1;
        const uint32_t* As = (const uint32_t*)(dsm + buf * STAGE);
        const uint32_t* Bs = (const uint32_t*)(dsm + buf * STAGE + A_BYTES);

        #pragma unroll
        for (int ks = 0; ks < 4; ks++) {
            uint32_t bfr[4][2];
            #pragma unroll
            for (int ni = 0; ni < 4; ni++) {
                if (TB) {
                    int base = (wn * 32 + ni * 8 + g) * ASTRF + ks * 8 + tg;
                    bfr[ni][0] = Bs[base];
                    bfr[ni][1] = Bs[base + 4];
                } else {
                    int base = (ks * 8 + tg) * BSTRF_KM + wn * 32 + ni * 8 + g;
                    bfr[ni][0] = Bs[base];
                    bfr[ni][1] = Bs[base + 4 * BSTRF_KM];
                }
            }
            #pragma unroll
            for (int mi = 0; mi < 4; mi++) {
                int ab = (wm * 64 + mi * 16 + g) * ASTRF + ks * 8 + tg;
                uint32_t af[4];
                af[0] = As[ab];
                af[1] = As[ab + 8 * ASTRF];
                af[2] = As[ab + 4];
                af[3] = As[ab + 8 * ASTRF + 4];
                #pragma unroll
                for (int ni = 0; ni < 4; ni++)
                    mma_tf32(acc[mi][ni], af, bfr[ni]);
            }
        }
        __syncthreads();
    }

    #pragma unroll
    for (int mi = 0; mi < 4; mi++) {
        #pragma unroll
        for (int ni = 0; ni < 4; ni++) {
            int n = nBase + wn * 32 + ni * 8 + tg * 2;
            if (n < N) {
                float bx = 0.f, by = 0.f;
                if (bias) { bx = bias[n]; by = bias[n + 1]; }
                #pragma unroll
                for (int rr = 0; rr < 2; rr++) {
                    int m = mBase + wm * 64 + mi * 16 + g + rr * 8;
                    float ox = acc[mi][ni][rr * 2 + 0] * alpha + bx;
                    float oy = acc[mi][ni][rr * 2 + 1] * alpha + by;
                    if (relu) { ox = fmaxf(ox, 0.f); oy = fmaxf(oy, 0.f); }
                    if (roundOut) { ox = rnd_tf32(ox); oy = rnd_tf32(oy); }
                    *(float2*)(C + cOff + (long long)m * ldc + n) = make_float2(ox, oy);
                }
            }
        }
    }
}

// ============ kernel 3: 64x256, 2-stage, 2 CTA/SM ===========================
// B k-major only. Requires M%64==0, N%256==0, K%32==0.
__global__ __launch_bounds__(256, 2)
void tf32_gemm3(const float* __restrict__ A, const float* __restrict__ B,
                float* __restrict__ C, int M, int N, int K,
                int lda, int ldb, int ldc,
                long long sA, long long sB,
                int zdiv, long long sC1, long long sC2,
                float alpha, const float* __restrict__ bias, int relu, int roundOut)
{
    extern __shared__ __align__(16) char dsm[];
    const uint32_t sBase = (uint32_t)__cvta_generic_to_shared(dsm);

    const int bz = blockIdx.z;
    A += (long long)bz * sA;
    B += (long long)bz * sB;
    const long long cOff = (long long)(bz / zdiv) * sC1 + (long long)(bz % zdiv) * sC2;

    const int mBase = blockIdx.y * 64;
    const int nBase = blockIdx.x * 256;
    const int tid   = threadIdx.x;
    const int lane  = tid & 31;
    const int warp  = tid >> 5;
    const int wm    = warp >> 2;     // 0..1 -> 32 rows
    const int wn    = warp & 3;      // 0..3 -> 64 cols
    const int g     = lane >> 2;
    const int tg    = lane & 3;

    float acc[2][8][4];
    #pragma unroll
    for (int i = 0; i < 2; i++)
        #pragma unroll
        for (int j = 0; j < 8; j++)
            #pragma unroll
            for (int e = 0; e < 4; e++) acc[i][j][e] = 0.0f;

    const int nk = K >> 5;

    auto load_tile = [&](int kt, int buf) {
        const int k0 = kt << 5;
        const uint32_t sb = sBase + buf * STAGE3;
        #pragma unroll
        for (int it = 0; it < 2; it++) {          // A: 64 rows x 8 chunks = 512
            int idx = tid + it * 256;
            int r = idx >> 3, c = idx & 7;
            cp16(sb + r * 144 + c * 16,
                 A + (long long)(mBase + r) * lda + k0 + c * 4);
        }
        #pragma unroll
        for (int it = 0; it < 8; it++) {          // B: 32 rows x 64 chunks = 2048
            int idx = tid + it * 256;
            int r = idx >> 6, c = idx & 63;
            cp16(sb + A3_BYTES + r * 1056 + c * 16,
                 B + (long long)(k0 + r) * ldb + nBase + c * 4);
        }
        asm volatile("cp.async.commit_group;" ::: "memory");
    };

    load_tile(0, 0);

    for (int kt = 0; kt < nk; kt++) {
        if (kt + 1 < nk) {
            load_tile(kt + 1, (kt + 1) & 1);
            asm volatile("cp.async.wait_group 1;" ::: "memory");
        } else {
            asm volatile("cp.async.wait_group 0;" ::: "memory");
        }
        __syncthreads();

        const int buf = kt & 1;
        const uint32_t* As = (const uint32_t*)(dsm + buf * STAGE3);
        const uint32_t* Bs = (const uint32_t*)(dsm + buf * STAGE3 + A3_BYTES);

        #pragma unroll
        for (int ks = 0; ks < 4; ks++) {
            uint32_t bfr[8][2];
            #pragma unroll
            for (int ni = 0; ni < 8; ni++) {
                int base = (ks * 8 + tg) * B3STR_KM + wn * 64 + ni * 8 + g;
                bfr[ni][0] = Bs[base];
                bfr[ni][1] = Bs[base + 4 * B3STR_KM];
            }
            #pragma unroll
            for (int mi = 0; mi < 2; mi++) {
                int ab = (wm * 32 + mi * 16 + g) * ASTRF + ks * 8 + tg;
                uint32_t af[4];
                af[0] = As[ab];
                af[1] = As[ab + 8 * ASTRF];
                af[2] = As[ab + 4];
                af[3] = As[ab + 8 * ASTRF + 4];
                #pragma unroll
                for (int ni = 0; ni < 8; ni++)
                    mma_tf32(acc[mi][ni], af, bfr[ni]);
            }
        }
        __syncthreads();
    }

    #pragma unroll
    for (int mi = 0; mi < 2; mi++) {
        #pragma unroll
        for (int ni = 0; ni < 8; ni++) {
            int n = nBase + wn * 64 + ni * 8 + tg * 2;
            float bx = 0.f, by = 0.f;
            if (bias) { bx = bias[n]; by = bias[n + 1]; }
            #pragma unroll
            for (int rr = 0; rr < 2; rr++) {
                int m = mBase + wm * 32 + mi * 16 + g + rr * 8;
                float ox = acc[mi][ni][rr * 2 + 0] * alpha + bx;
                float oy = acc[mi][ni][rr * 2 + 1] * alpha + by;
                if (relu) { ox = fmaxf(ox, 0.f); oy = fmaxf(oy, 0.f); }
                if (roundOut) { ox = rnd_tf32(ox); oy = rnd_tf32(oy); }
                *(float2*)(C + cOff + (long long)m * ldc + n) = make_float2(ox, oy);
            }
        }
    }
}

// ============ flash attention ==============================================
__global__ __launch_bounds__(256, 1)
void flash_attn(const float* __restrict__ QK, const float* __restrict__ Vg,
                float* __restrict__ AT, float scale)
{
    extern __shared__ __align__(16) float fs[];
    const uint32_t sb = (uint32_t)__cvta_generic_to_shared(fs);

    const int half = blockIdx.x, mb = blockIdx.y, z = blockIdx.z;
    const int h = z >> 3, b = z & 7;
    const int tid = threadIdx.x, lane = tid & 31, warp = tid >> 5;
    const int wm = warp >> 2, wn = warp & 3, g = lane >> 2, tg = lane & 3;

    const long long qBase = (long long)h * 1048576 + (long long)(b * 1024 + mb * 128) * 128;
    const long long kBase = (long long)h * 1048576 + (long long)(b * 1024) * 128 + 64;
    const long long vBase = (long long)h * 4194304 + (long long)(b * 1024) * 512 + half * 256;

    #pragma unroll
    for (int it = 0; it < 8; it++) {
        int idx = tid + it * 256, r = idx >> 4, c = (idx & 15) << 2;
        cp16(sb + (FQ + r * 68 + c) * 4, QK + qBase + r * 128 + c);
    }
    #pragma unroll
    for (int it = 0; it < 4; it++) {
        int idx = tid + it * 256, r = idx >> 4, c = (idx & 15) << 2;
        cp16(sb + (FK + r * 68 + c) * 4, QK + kBase + r * 128 + c);
    }
    asm volatile("cp.async.commit_group;" ::: "memory");
    asm volatile("cp.async.wait_group 0;" ::: "memory");

    float acc[4][8][4];
    #pragma unroll
    for (int i = 0; i < 4; i++)
        #pragma unroll
        for (int j = 0; j < 8; j++)
            #pragma unroll
            for (int e = 0; e < 4; e++) acc[i][j][e] = 0.0f;
    float rs[4][2];
    #pragma unroll
    for (int i = 0; i < 4; i++) { rs[i][0] = 0.f; rs[i][1] = 0.f; }

    for (int kt = 0; kt < 16; kt++) {
        __syncthreads();
        const float* vsrc = Vg + vBase + (long long)(kt * 64) * 512;
        #pragma unroll
        for (int it = 0; it < 8; it++) {
            int idx = tid + it * 256, r = idx >> 5, c = (idx & 31) << 2;
            cp16(sb + (FV0 + r * 136 + c) * 4, vsrc + r * 512 + c);
        }
        asm volatile("cp.async.commit_group;" ::: "memory");

        float accs[4][2][4];
        #pragma unroll
        for (int i = 0; i < 4; i++)
            #pragma unroll
            for (int j = 0; j < 2; j++)
                #pragma unroll
                for (int e = 0; e < 4; e++) accs[i][j][e] = 0.0f;
        #pragma unroll
        for (int ks = 0; ks < 8; ks++) {
            uint32_t bf[2][2];
            #pragma unroll
            for (int ni = 0; ni < 2; ni++) {
                int base = FK + (wn * 16 + ni * 8 + g) * 68 + ks * 8 + tg;
                bf[ni][0] = __float_as_uint(fs[base]);
                bf[ni][1] = __float_as_uint(fs[base + 4]);
            }
            #pragma unroll
            for (int mi = 0; mi < 4; mi++) {
                int ab = FQ + (wm * 64 + mi * 16 + g) * 68 + ks * 8 + tg;
                uint32_t af[4];
                af[0] = __float_as_uint(fs[ab]);
                af[1] = __float_as_uint(fs[ab + 8 * 68]);
                af[2] = __float_as_uint(fs[ab + 4]);
                af[3] = __float_as_uint(fs[ab + 8 * 68 + 4]);
                #pragma unroll
                for (int ni = 0; ni < 2; ni++)
                    mma_tf32(accs[mi][ni], af, bf[ni]);
            }
        }
        #pragma unroll
        for (int mi = 0; mi < 4; mi++) {
            int row = wm * 64 + mi * 16 + g;
            #pragma unroll
            for (int ni = 0; ni < 2; ni++) {
                int col = wn * 16 + ni * 8 + tg * 2;
                float e0 = rnd_tf32(__expf(accs[mi][ni][0] * scale));
                float e1 = rnd_tf32(__expf(accs[mi][ni][1] * scale));
                float e2 = rnd_tf32(__expf(accs[mi][ni][2] * scale));
                float e3 = rnd_tf32(__expf(accs[mi][ni][3] * scale));
                rs[mi][0] += e0 + e1;
                rs[mi][1] += e2 + e3;
                *(float2*)&fs[FE + row * 68 + col]       = make_float2(e0, e1);
                *(float2*)&fs[FE + (row + 8) * 68 + col] = make_float2(e2, e3);
            }
        }
        __syncthreads();

        if (kt < 15) {
            const float* ksrc = QK + kBase + (long long)((kt + 1) * 64) * 128;
            #pragma unroll
            for (int it = 0; it < 4; it++) {
                int idx = tid + it * 256, r = idx >> 4, c = (idx & 15) << 2;
                cp16(sb + (FK + r * 68 + c) * 4, ksrc + r * 128 + c);
            }
        }
        #pragma unroll
        for (int it = 0; it < 8; it++) {
            int idx = tid + it * 256, r = idx >> 5, c = (idx & 31) << 2;
            cp16(sb + (FV1 + r * 136 + c) * 4, vsrc + 128 + r * 512 + c);
        }
        asm volatile("cp.async.commit_group;" ::: "memory");

        asm volatile("cp.async.wait_group 1;" ::: "memory");
        #pragma unroll
        for (int ks = 0; ks < 8; ks++) {
            uint32_t bf[4][2];
            #pragma unroll
            for (int ni = 0; ni < 4; ni++) {
                int base = FV0 + (ks * 8 + tg) * 136 + wn * 32 + ni * 8 + g;
                bf[ni][0] = __float_as_uint(fs[base]);
                bf[ni][1] = __float_as_uint(fs[base + 4 * 136]);
            }
            #pragma unroll
            for (int mi = 0; mi < 4; mi++) {
                int ab = FE + (wm * 64 + mi * 16 + g) * 68 + ks * 8 + tg;
                uint32_t af[4];
                af[0] = __float_as_uint(fs[ab]);
                af[1] = __float_as_uint(fs[ab + 8 * 68]);
                af[2] = __float_as_uint(fs[ab + 4]);
                af[3] = __float_as_uint(fs[ab + 8 * 68 + 4]);
                #pragma unroll
                for (int ni = 0; ni < 4; ni++)
                    mma_tf32(acc[mi][ni], af, bf[ni]);
            }
        }
        asm volatile("cp.async.wait_group 0;" ::: "memory");
        #pragma unroll
        for (int ks = 0; ks < 8; ks++) {
            uint32_t bf[4][2];
            #pragma unroll
            for (int ni = 0; ni < 4; ni++) {
                int base = FV1 + (ks * 8 + tg) * 136 + wn * 32 + ni * 8 + g;
                bf[ni][0] = __float_as_uint(fs[base]);
                bf[ni][1] = __float_as_uint(fs[base + 4 * 136]);
            }
            #pragma unroll
            for (int mi = 0; mi < 4; mi++) {
                int ab = FE + (wm * 64 + mi * 16 + g) * 68 + ks * 8 + tg;
                uint32_t af[4];
                af[0] = __float_as_uint(fs[ab]);
                af[1] = __float_as_uint(fs[ab + 8 * 68]);
                af[2] = __float_as_uint(fs[ab + 4]);
                af[3] = __float_as_uint(fs[ab + 8 * 68 + 4]);
                #pragma unroll
                for (int ni = 0; ni < 4; ni++)
                    mma_tf32(acc[mi][4 + ni], af, bf[ni]);
            }
        }
    }

    #pragma unroll
    for (int mi = 0; mi < 4; mi++)
        #pragma unroll
        for (int rr = 0; rr < 2; rr++) {
            float v = rs[mi][rr];
            v += __shfl_xor_sync(0xffffffffu, v, 1);
            v += __shfl_xor_sync(0xffffffffu, v, 2);
            if (tg == 0)
                fs[FRS + (wm * 64 + mi * 16 + g + rr * 8) * 4 + wn] = v;
        }
    __syncthreads();
    if (tid < 128)
        fs[FINV + tid] = 1.0f / (fs[FRS + tid * 4] + fs[FRS + tid * 4 + 1] +
                                 fs[FRS + tid * 4 + 2] + fs[FRS + tid * 4 + 3]);
    __syncthreads();

    #pragma unroll
    for (int mi = 0; mi < 4; mi++) {
        #pragma unroll
        for (int rr = 0; rr < 2; rr++) {
            int row = wm * 64 + mi * 16 + g + rr * 8;
            float inv = fs[FINV + row];
            long long mg = (long long)(b * 1024 + mb * 128 + row);
            #pragma unroll
            for (int j = 0; j < 8; j++) {
                int chunk = j >> 2, ni = j & 3;
                int col = h * 512 + half * 256 + chunk * 128 + wn * 32 + ni * 8 + tg * 2;
                float ox = rnd_tf32(acc[mi][j][rr * 2 + 0] * inv);
                float oy = rnd_tf32(acc[mi][j][rr * 2 + 1] * inv);
                *(float2*)(AT + mg * 4096 + col) = make_float2(ox, oy);
            }
        }
    }
}

// ---------------- elementwise kernels ---------------------------------------

__global__ __launch_bounds__(256)
void round_copy(const float4* __restrict__ src, float4* __restrict__ dst, int n4)
{
    int i = blockIdx.x * 256 + threadIdx.x;
    if (i < n4) {
        float4 v = src[i];
        v.x = rnd_tf32(v.x); v.y = rnd_tf32(v.y);
        v.z = rnd_tf32(v.z); v.w = rnd_tf32(v.w);
        dst[i] = v;
    }
}

__global__ __launch_bounds__(256)
void round_concat(const float4* __restrict__ src, float* __restrict__ dst,
                  int n4, int colOff)
{
    int i = blockIdx.x * 256 + threadIdx.x;
    if (i < n4) {
        float4 v = src[i];
        v.x = rnd_tf32(v.x); v.y = rnd_tf32(v.y);
        v.z = rnd_tf32(v.z); v.w = rnd_tf32(v.w);
        int row = i >> 4;
        int c4  = i & 15;
        *(float4*)(dst + (long long)row * 128 + colOff + c4 * 4) = v;
    }
}

__global__ __launch_bounds__(128)
void add_ln512(const float* __restrict__ X, const float* __restrict__ Y,
               const float* __restrict__ gamma, const float* __restrict__ beta,
               float* __restrict__ O, int roundOut)
{
    __shared__ float red[4];
    const long long row = blockIdx.x;
    const int tid = threadIdx.x;

    const float4 x4 = ((const float4*)(X + row * 512))[tid];
    const float4 y4 = ((const float4*)(Y + row * 512))[tid];
    float4 v;
    v.x = x4.x + y4.x; v.y = x4.y + y4.y; v.z = x4.z + y4.z; v.w = x4.w + y4.w;

    float s = (v.x + v.y) + (v.z + v.w);
    #pragma unroll
    for (int o = 16; o > 0; o >>= 1) s += __shfl_xor_sync(0xffffffffu, s, o);
    if ((tid & 31) == 0) red[tid >> 5] = s;
    __syncthreads();
    const float mean = ((red[0] + red[1]) + (red[2] + red[3])) * (1.0f / 512.0f);
    __syncthreads();

    float q = v.x * v.x + v.y * v.y + v.z * v.z + v.w * v.w;
    #pragma unroll
    for (int o = 16; o > 0; o >>= 1) q += __shfl_xor_sync(0xffffffffu, q, o);
    if ((tid & 31) == 0) red[tid >> 5] = q;
    __syncthreads();
    const float var = ((red[0] + red[1]) + (red[2] + red[3])) * (1.0f / 512.0f) - mean * mean;
    const float inv = rsqrtf(var + 1e-3f);

    const int n = tid * 4;
    const float4 g4 = *(const float4*)(gamma + n);
    const float4 b4 = *(const float4*)(beta + n);
    float4 o;
    o.x = g4.x * (v.x - mean) * inv + b4.x;
    o.y = g4.y * (v.y - mean) * inv + b4.y;
    o.z = g4.z * (v.z - mean) * inv + b4.z;
    o.w = g4.w * (v.w - mean) * inv + b4.w;
    if (roundOut) {
        o.x = rnd_tf32(o.x); o.y = rnd_tf32(o.y);
        o.z = rnd_tf32(o.z); o.w = rnd_tf32(o.w);
    }
    ((float4*)(O + row * 512))[tid] = o;
}

// ---------------------------------------------------------------------------

static void run_gemm1(bool tb, const float* A, const float* B, float* C,
                      int M, int N, int K, int lda, int ldb, int ldc,
                      long long sA, long long sB,
                      int zdiv, long long sC1, long long sC2,
                      int batch, float alpha, const float* bias, int relu, int rOut)
{
    dim3 grid((N + BN - 1) / BN, M / BM, batch);
    if (tb)
        tf32_gemm<true><<<grid, 256, SMEM_BYTES>>>(A, B, C, M, N, K, lda, ldb, ldc,
            sA, sB, zdiv, sC1, sC2, alpha, bias, relu, rOut);
    else
        tf32_gemm<false><<<grid, 256, SMEM_BYTES>>>(A, B, C, M, N, K, lda, ldb, ldc,
            sA, sB, zdiv, sC1, sC2, alpha, bias, relu, rOut);
}

static void run_gemm3(const float* A, const float* B, float* C,
                      int M, int N, int K, int lda, int ldb, int ldc,
                      long long sA, long long sB,
                      int zdiv, long long sC1, long long sC2,
                      int batch, float alpha, const float* bias, int relu, int rOut)
{
    dim3 grid(N / 256, M / 64, batch);
    tf32_gemm3<<<grid, 256, SMEM3>>>(A, B, C, M, N, K, lda, ldb, ldc,
        sA, sB, zdiv, sC1, sC2, alpha, bias, relu, rOut);
}

static void run_round(const float* src, float* dst, int n)
{
    int n4 = n / 4;
    round_copy<<<(n4 + 255) / 256, 256>>>((const float4*)src, (float4*)dst, n4);
}

struct Ptrs {
    float *qk, *v, *at, *mha, *h, *f1, *f2;
    float *xr, *qkw, *vwr, *lwr, *w1r, *w2r;
};

static Ptrs get_ptrs()
{
    static Ptrs p;
    static bool init = false;
    if (!init) {
        cudaGetSymbolAddress((void**)&p.qk,  g_qk);
        cudaGetSymbolAddress((void**)&p.v,   g_v);
        cudaGetSymbolAddress((void**)&p.at,  g_at);
        cudaGetSymbolAddress((void**)&p.mha, g_mha);
        cudaGetSymbolAddress((void**)&p.h,   g_h);
        cudaGetSymbolAddress((void**)&p.f1,  g_f1);
        cudaGetSymbolAddress((void**)&p.f2,  g_f2);
        cudaGetSymbolAddress((void**)&p.xr,  g_xr);
        cudaGetSymbolAddress((void**)&p.qkw, g_qkw);
        cudaGetSymbolAddress((void**)&p.vwr, g_vwr);
        cudaGetSymbolAddress((void**)&p.lwr, g_lwr);
        cudaGetSymbolAddress((void**)&p.w1r, g_w1r);
        cudaGetSymbolAddress((void**)&p.w2r, g_w2r);
        cudaFuncSetAttribute(tf32_gemm<true>,  cudaFuncAttributeMaxDynamicSharedMemorySize, SMEM_BYTES);
        cudaFuncSetAttribute(tf32_gemm<false>, cudaFuncAttributeMaxDynamicSharedMemorySize, SMEM_BYTES);
        cudaFuncSetAttribute(tf32_gemm3,       cudaFuncAttributeMaxDynamicSharedMemorySize, SMEM3);
        cudaFuncSetAttribute(flash_attn,       cudaFuncAttributeMaxDynamicSharedMemorySize, FLASH_SMEM);
        init = true;
    }
    return p;
}

extern "C" void kernel_launch(void* const* d_in, const int* in_sizes, int n_in,
                              void* d_out, int out_size)
{
    const float* x      = (const float*)d_in[0];   // [8,1024,512]
    const float* qw     = (const float*)d_in[1];   // [8,512,64]
    const float* kw     = (const float*)d_in[2];   // [8,512,64]
    const float* vw     = (const float*)d_in[3];   // [8,512,512]
    const float* lw     = (const float*)d_in[4];   // [4096,512]
    const float* gamma1 = (const float*)d_in[5];
    const float* beta1  = (const float*)d_in[6];
    const float* w1     = (const float*)d_in[7];   // [512,2048]
    const float* b1     = (const float*)d_in[8];
    const float* w2     = (const float*)d_in[9];   // [2048,512]
    const float* b2     = (const float*)d_in[10];
    const float* gamma2 = (const float*)d_in[11];
    const float* beta2  = (const float*)d_in[12];
    float* out = (float*)d_out;

    Ptrs p = get_ptrs();
    const int M = 8192;
    const float scale = 0.044194173824159216f;  // 1/sqrt(512)

    // tf32 rounding of raw inputs; qw|kw concatenated to [8][512][128]
    run_round(x,  p.xr,  4194304);
    round_concat<<<(65536 + 255) / 256, 256>>>((const float4*)qw, p.qkw, 65536, 0);
    round_concat<<<(65536 + 255) / 256, 256>>>((const float4*)kw, p.qkw, 65536, 64);
    run_round(vw, p.vwr, 2097152);
    run_round(lw, p.lwr, 2097152);
    run_round(w1, p.w1r, 1048576);
    run_round(w2, p.w2r, 1048576);

    // QK = x @ [qw|kw][h] -> [H][8192][128] (rounded out)
    run_gemm1(false, p.xr, p.qkw, p.qk, M, 128, 512, 512, 128, 128,
              0LL, 65536LL, 1, 1048576LL, 0LL, 8, 1.0f, nullptr, 0, 1);
    // V = x @ vw[h] -> [H][8192][512] (rounded out)
    run_gemm3(p.xr, p.vwr, p.v, M, 512, 512, 512, 512, 512,
              0LL, 262144LL, 1, 4194304LL, 0LL, 8, 1.0f, nullptr, 0, 1);

    // fused attention: softmax(scale * Q K^T) @ V -> g_at (concat, rounded)
    flash_attn<<<dim3(2, 8, 64), 256, FLASH_SMEM>>>(p.qk, p.v, p.at, scale);

    // mha = attn @ lw (fp32)
    run_gemm3(p.at, p.lwr, p.mha, M, 512, 4096, 4096, 512, 512,
              0LL, 0LL, 1, 0LL, 0LL, 1, 1.0f, nullptr, 0, 0);

    // h = LN(x + mha)  (rounded: feeds FFN1)
    add_ln512<<<8192, 128>>>(x, p.mha, gamma1, beta1, p.h, 1);

    // f1 = relu(h @ w1 + b1) (rounded out)
    run_gemm3(p.h, p.w1r, p.f1, M, 2048, 512, 512, 2048, 2048,
              0LL, 0LL, 1, 0LL, 0LL, 1, 1.0f, b1, 1, 1);
    // f2 = f1 @ w2 + b2 (fp32)
    run_gemm3(p.f1, p.w2r, p.f2, M, 512, 2048, 2048, 512, 512,
              0LL, 0LL, 1, 0LL, 0LL, 1, 1.0f, b2, 0, 0);

    // out = LN(h + f2)
    add_ln512<<<8192, 128>>>(p.h, p.f2, gamma2, beta2, out, 0);
}

// round 16
// speedup vs baseline: 1.0351x; 1.0351x over previous
#include <cuda_runtime.h>
#include <cstdint>

// ---------------- scratch (device globals; no allocation allowed) -----------
__device__ float g_qk[8388608];    // [H][8192][128]  q(0:64) | k(64:128)
__device__ float g_v [33554432];   // [H][8192][512]
__device__ float g_at[33554432];   // [8192][4096] concat heads
__device__ float g_mha[4194304];
__device__ float g_h [4194304];
__device__ float g_f1[16777216];   // [8192][2048]
__device__ float g_f2[4194304];
// tf32-rounded copies of raw inputs
__device__ float g_xr [4194304];
__device__ float g_qkw[524288];    // [8][512][128] concat qw|kw rounded
__device__ float g_vwr[2097152];
__device__ float g_lwr[2097152];
__device__ float g_w1r[1048576];
__device__ float g_w2r[1048576];

// ---- kernel 1: 128x128 tile, 2-stage, 2 CTA/SM ----
#define BM 128
#define BN 128
#define ASTRF   36
#define BSTRF_KM 136
#define A_BYTES 18432
#define STAGE   36864
#define SMEM_BYTES 73728

// ---- kernel 2: 128x256 tile, 3-stage, 1 CTA/SM (best measured: R13) ----
#define A2_BYTES 18432
#define B2STR_KM 264
#define STAGE2   55296
#define SMEM2    165888

// ---- flash attention smem layout (floats) ----
#define FQ   0        // Q  [128][68]
#define FK   8704     // K  [64][68]
#define FE   13056    // E  [128][68]
#define FV0  21760    // V chunk buf0 [64][136]
#define FV1  30464    // V chunk buf1 [64][136]
#define FRS  39168    // row-sum partials [128][4]
#define FINV 39680    // inv row sums [128]
#define FLASH_SMEM 159232

__device__ __forceinline__ void cp16(uint32_t dst, const void* src) {
    asm volatile("cp.async.cg.shared.global [%0], [%1], 16;" :: "r"(dst), "l"(src));
}
__device__ __forceinline__ void cp16z(uint32_t dst, const void* src) {
    asm volatile("cp.async.cg.shared.global [%0], [%1], 16, %2;"
                 :: "r"(dst), "l"(src), "r"(0));
}
__device__ __forceinline__ float rnd_tf32(float f) {
    uint32_t r;
    asm("cvt.rna.tf32.f32 %0, %1;" : "=r"(r) : "f"(f));
    return __uint_as_float(r);
}
__device__ __forceinline__ void mma_tf32(float* c, const uint32_t* a, const uint32_t* b) {
    asm volatile(
        "mma.sync.aligned.m16n8k8.row.col.f32.tf32.tf32.f32 "
        "{%0,%1,%2,%3},{%4,%5,%6,%7},{%8,%9},{%0,%1,%2,%3};"
        : "+f"(c[0]), "+f"(c[1]), "+f"(c[2]), "+f"(c[3])
        : "r"(a[0]), "r"(a[1]), "r"(a[2]), "r"(a[3]), "r"(b[0]), "r"(b[1]));
}

// ============ kernel 1: 128x128 (QK projection, N=128) ======================
template<bool TB>
__global__ __launch_bounds__(256, 2)
void tf32_gemm(const float* __restrict__ A, const float* __restrict__ B,
               float* __restrict__ C, int M, int N, int K,
               int lda, int ldb, int ldc,
               long long sA, long long sB,
               int zdiv, long long sC1, long long sC2,
               float alpha, const float* __restrict__ bias, int relu, int roundOut)
{
    extern __shared__ __align__(16) char dsm[];
    const uint32_t sBase = (uint32_t)__cvta_generic_to_shared(dsm);

    const int bz = blockIdx.z;
    A += (long long)bz * sA;
    B += (long long)bz * sB;
    const long long cOff = (long long)(bz / zdiv) * sC1 + (long long)(bz % zdiv) * sC2;

    const int mBase = blockIdx.y * BM;
    const int nBase = blockIdx.x * BN;
    const int tid   = threadIdx.x;
    const int lane  = tid & 31;
    const int warp  = tid >> 5;
    const int wm    = warp >> 2;
    const int wn    = warp & 3;
    const int g     = lane >> 2;
    const int tg    = lane & 3;

    float acc[4][4][4];
    #pragma unroll
    for (int i = 0; i < 4; i++)
        #pragma unroll
        for (int j = 0; j < 4; j++)
            #pragma unroll
            for (int e = 0; e < 4; e++) acc[i][j][e] = 0.0f;

    const int nk = K >> 5;

    auto load_tile = [&](int kt, int buf) {
        const int k0 = kt << 5;
        const uint32_t sb = sBase + buf * STAGE;
        #pragma unroll
        for (int it = 0; it < 4; it++) {
            int idx = tid + it * 256;
            int r = idx >> 3, c = idx & 7;
            cp16(sb + r * 144 + c * 16,
                 A + (long long)(mBase + r) * lda + k0 + c * 4);
        }
        if (TB) {
            #pragma unroll
            for (int it = 0; it < 4; it++) {
                int idx = tid + it * 256;
                int r = idx >> 3, c = idx & 7;
                int gn = nBase + r;
                uint32_t dst = sb + A_BYTES + r * 144 + c * 16;
                if (gn < N) cp16(dst, B + (long long)gn * ldb + k0 + c * 4);
                else        cp16z(dst, B);
            }
        } else {
            #pragma unroll
            for (int it = 0; it < 4; it++) {
                int idx = tid + it * 256;
                int r = idx >> 5, cc = idx & 31;
                int gn = nBase + cc * 4;
                uint32_t dst = sb + A_BYTES + r * 544 + cc * 16;
                if (gn < N) cp16(dst, B + (long long)(k0 + r) * ldb + gn);
                else        cp16z(dst, B);
            }
        }
        asm volatile("cp.async.commit_group;" ::: "memory");
    };

    load_tile(0, 0);

    for (int kt = 0; kt < nk; kt++) {
        if (kt + 1 < nk) {
            load_tile(kt + 1, (kt + 1) & 1);
            asm volatile("cp.async.wait_group 1;" ::: "memory");
        } else {
            asm volatile("cp.async.wait_group 0;" ::: "memory");
        }
        __syncthreads();

        const int buf = kt & 1;
        const uint32_t* As = (const uint32_t*)(dsm + buf * STAGE);
        const uint32_t* Bs = (const uint32_t*)(dsm + buf * STAGE + A_BYTES);

        #pragma unroll
        for (int ks = 0; ks < 4; ks++) {
            uint32_t bfr[4][2];
            #pragma unroll
            for (int ni = 0; ni < 4; ni++) {
                if (TB) {
                    int base = (wn * 32 + ni * 8 + g) * ASTRF + ks * 8 + tg;
                    bfr[ni][0] = Bs[base];
                    bfr[ni][1] = Bs[base + 4];
                } else {
                    int base = (ks * 8 + tg) * BSTRF_KM + wn * 32 + ni * 8 + g;
                    bfr[ni][0] = Bs[base];
                    bfr[ni][1] = Bs[base + 4 * BSTRF_KM];
                }
            }
            #pragma unroll
            for (int mi = 0; mi < 4; mi++) {
                int ab = (wm * 64 + mi * 16 + g) * ASTRF + ks * 8 + tg;
                uint32_t af[4];
                af[0] = As[ab];
                af[1] = As[ab + 8 * ASTRF];
                af[2] = As[ab + 4];
                af[3] = As[ab + 8 * ASTRF + 4];
                #pragma unroll
                for (int ni = 0; ni < 4; ni++)
                    mma_tf32(acc[mi][ni], af, bfr[ni]);
            }
        }
        __syncthreads();
    }

    #pragma unroll
    for (int mi = 0; mi < 4; mi++) {
        #pragma unroll
        for (int ni = 0; ni < 4; ni++) {
            int n = nBase + wn * 32 + ni * 8 + tg * 2;
            if (n < N) {
                float bx = 0.f, by = 0.f;
                if (bias) { bx = bias[n]; by = bias[n + 1]; }
                #pragma unroll
                for (int rr = 0; rr < 2; rr++) {
                    int m = mBase + wm * 64 + mi * 16 + g + rr * 8;
                    float ox = acc[mi][ni][rr * 2 + 0] * alpha + bx;
                    float oy = acc[mi][ni][rr * 2 + 1] * alpha + by;
                    if (relu) { ox = fmaxf(ox, 0.f); oy = fmaxf(oy, 0.f); }
                    if (roundOut) { ox = rnd_tf32(ox); oy = rnd_tf32(oy); }
                    *(float2*)(C + cOff + (long long)m * ldc + n) = make_float2(ox, oy);
                }
            }
        }
    }
}

// ============ kernel 2: 128x256, 3-stage, k-major B (R13 config) ============
__global__ __launch_bounds__(256, 1)
void tf32_gemm2(const float* __restrict__ A, const float* __restrict__ B,
                float* __restrict__ C, int M, int N, int K,
                int lda, int ldb, int ldc,
                long long sA, long long sB,
                int zdiv, long long sC1, long long sC2,
                float alpha, const float* __restrict__ bias, int relu, int roundOut)
{
    extern __shared__ __align__(16) char dsm[];
    const uint32_t sBase = (uint32_t)__cvta_generic_to_shared(dsm);

    const int bz = blockIdx.z;
    A += (long long)bz * sA;
    B += (long long)bz * sB;
    const long long cOff = (long long)(bz / zdiv) * sC1 + (long long)(bz % zdiv) * sC2;

    const int mBase = blockIdx.y * 128;
    const int nBase = blockIdx.x * 256;
    const int tid   = threadIdx.x;
    const int lane  = tid & 31;
    const int warp  = tid >> 5;
    const int wm    = warp >> 2;
    const int wn    = warp & 3;
    const int g     = lane >> 2;
    const int tg    = lane & 3;

    float acc[4][8][4];
    #pragma unroll
    for (int i = 0; i < 4; i++)
        #pragma unroll
        for (int j = 0; j < 8; j++)
            #pragma unroll
            for (int e = 0; e < 4; e++) acc[i][j][e] = 0.0f;

    const int nk = K >> 5;

    auto load_tile = [&](int kt, int buf) {
        const int k0 = kt << 5;
        const uint32_t sb = sBase + buf * STAGE2;
        #pragma unroll
        for (int it = 0; it < 4; it++) {
            int idx = tid + it * 256;
            int r = idx >> 3, c = idx & 7;
            cp16(sb + r * 144 + c * 16,
                 A + (long long)(mBase + r) * lda + k0 + c * 4);
        }
        #pragma unroll
        for (int it = 0; it < 8; it++) {
            int idx = tid + it * 256;
            int r = idx >> 6, c = idx & 63;
            cp16(sb + A2_BYTES + r * 1056 + c * 16,
                 B + (long long)(k0 + r) * ldb + nBase + c * 4);
        }
        asm volatile("cp.async.commit_group;" ::: "memory");
    };

    load_tile(0, 0);
    if (nk > 1) load_tile(1, 1);

    for (int kt = 0; kt < nk; kt++) {
        if (kt + 1 < nk) asm volatile("cp.async.wait_group 1;" ::: "memory");
        else             asm volatile("cp.async.wait_group 0;" ::: "memory");
        __syncthreads();
        if (kt + 2 < nk) load_tile(kt + 2, (kt + 2) % 3);

        const int buf = kt % 3;
        const uint32_t* As = (const uint32_t*)(dsm + buf * STAGE2);
        const uint32_t* Bs = (const uint32_t*)(dsm + buf * STAGE2 + A2_BYTES);

        #pragma unroll
        for (int ks = 0; ks < 4; ks++) {
            uint32_t bfr[8][2];
            #pragma unroll
            for (int ni = 0; ni < 8; ni++) {
                int base = (ks * 8 + tg) * B2STR_KM + wn * 64 + ni * 8 + g;
                bfr[ni][0] = Bs[base];
                bfr[ni][1] = Bs[base + 4 * B2STR_KM];
            }
            #pragma unroll
            for (int mi = 0; mi < 4; mi++) {
                int ab = (wm * 64 + mi * 16 + g) * ASTRF + ks * 8 + tg;
                uint32_t af[4];
                af[0] = As[ab];
                af[1] = As[ab + 8 * ASTRF];
                af[2] = As[ab + 4];
                af[3] = As[ab + 8 * ASTRF + 4];
                #pragma unroll
                for (int ni = 0; ni < 8; ni++)
                    mma_tf32(acc[mi][ni], af, bfr[ni]);
            }
        }
        __syncthreads();
    }

    #pragma unroll
    for (int mi = 0; mi < 4; mi++) {
        #pragma unroll
        for (int ni = 0; ni < 8; ni++) {
            int n = nBase + wn * 64 + ni * 8 + tg * 2;
            float bx = 0.f, by = 0.f;
            if (bias) { bx = bias[n]; by = bias[n + 1]; }
            #pragma unroll
            for (int rr = 0; rr < 2; rr++) {
                int m = mBase + wm * 64 + mi * 16 + g + rr * 8;
                float ox = acc[mi][ni][rr * 2 + 0] * alpha + bx;
                float oy = acc[mi][ni][rr * 2 + 1] * alpha + by;
                if (relu) { ox = fmaxf(ox, 0.f); oy = fmaxf(oy, 0.f); }
                if (roundOut) { ox = rnd_tf32(ox); oy = rnd_tf32(oy); }
                *(float2*)(C + cOff + (long long)m * ldc + n) = make_float2(ox, oy);
            }
        }
    }
}

// ============ flash attention ==============================================
__global__ __launch_bounds__(256, 1)
void flash_attn(const float* __restrict__ QK, const float* __restrict__ Vg,
                float* __restrict__ AT, float scale)
{
    extern __shared__ __align__(16) float fs[];
    const uint32_t sb = (uint32_t)__cvta_generic_to_shared(fs);

    const int half = blockIdx.x, mb = blockIdx.y, z = blockIdx.z;
    const int h = z >> 3, b = z & 7;
    const int tid = threadIdx.x, lane = tid & 31, warp = tid >> 5;
    const int wm = warp >> 2, wn = warp & 3, g = lane >> 2, tg = lane & 3;

    const long long qBase = (long long)h * 1048576 + (long long)(b * 1024 + mb * 128) * 128;
    const long long kBase = (long long)h * 1048576 + (long long)(b * 1024) * 128 + 64;
    const long long vBase = (long long)h * 4194304 + (long long)(b * 1024) * 512 + half * 256;

    #pragma unroll
    for (int it = 0; it < 8; it++) {
        int idx = tid + it * 256, r = idx >> 4, c = (idx & 15) << 2;
        cp16(sb + (FQ + r * 68 + c) * 4, QK + qBase + r * 128 + c);
    }
    #pragma unroll
    for (int it = 0; it < 4; it++) {
        int idx = tid + it * 256, r = idx >> 4, c = (idx & 15) << 2;
        cp16(sb + (FK + r * 68 + c) * 4, QK + kBase + r * 128 + c);
    }
    asm volatile("cp.async.commit_group;" ::: "memory");
    asm volatile("cp.async.wait_group 0;" ::: "memory");

    float acc[4][8][4];
    #pragma unroll
    for (int i = 0; i < 4; i++)
        #pragma unroll
        for (int j = 0; j < 8; j++)
            #pragma unroll
            for (int e = 0; e < 4; e++) acc[i][j][e] = 0.0f;
    float rs[4][2];
    #pragma unroll
    for (int i = 0; i < 4; i++) { rs[i][0] = 0.f; rs[i][1] = 0.f; }

    for (int kt = 0; kt < 16; kt++) {
        __syncthreads();
        const float* vsrc = Vg + vBase + (long long)(kt * 64) * 512;
        #pragma unroll
        for (int it = 0; it < 8; it++) {
            int idx = tid + it * 256, r = idx >> 5, c = (idx & 31) << 2;
            cp16(sb + (FV0 + r * 136 + c) * 4, vsrc + r * 512 + c);
        }
        asm volatile("cp.async.commit_group;" ::: "memory");

        float accs[4][2][4];
        #pragma unroll
        for (int i = 0; i < 4; i++)
            #pragma unroll
            for (int j = 0; j < 2; j++)
                #pragma unroll
                for (int e = 0; e < 4; e++) accs[i][j][e] = 0.0f;
        #pragma unroll
        for (int ks = 0; ks < 8; ks++) {
            uint32_t bf[2][2];
            #pragma unroll
            for (int ni = 0; ni < 2; ni++) {
                int base = FK + (wn * 16 + ni * 8 + g) * 68 + ks * 8 + tg;
                bf[ni][0] = __float_as_uint(fs[base]);
                bf[ni][1] = __float_as_uint(fs[base + 4]);
            }
            #pragma unroll
            for (int mi = 0; mi < 4; mi++) {
                int ab = FQ + (wm * 64 + mi * 16 + g) * 68 + ks * 8 + tg;
                uint32_t af[4];
                af[0] = __float_as_uint(fs[ab]);
                af[1] = __float_as_uint(fs[ab + 8 * 68]);
                af[2] = __float_as_uint(fs[ab + 4]);
                af[3] = __float_as_uint(fs[ab + 8 * 68 + 4]);
                #pragma unroll
                for (int ni = 0; ni < 2; ni++)
                    mma_tf32(accs[mi][ni], af, bf[ni]);
            }
        }
        #pragma unroll
        for (int mi = 0; mi < 4; mi++) {
            int row = wm * 64 + mi * 16 + g;
            #pragma unroll
            for (int ni = 0; ni < 2; ni++) {
                int col = wn * 16 + ni * 8 + tg * 2;
                float e0 = rnd_tf32(__expf(accs[mi][ni][0] * scale));
                float e1 = rnd_tf32(__expf(accs[mi][ni][1] * scale));
                float e2 = rnd_tf32(__expf(accs[mi][ni][2] * scale));
                float e3 = rnd_tf32(__expf(accs[mi][ni][3] * scale));
                rs[mi][0] += e0 + e1;
                rs[mi][1] += e2 + e3;
                *(float2*)&fs[FE + row * 68 + col]       = make_float2(e0, e1);
                *(float2*)&fs[FE + (row + 8) * 68 + col] = make_float2(e2, e3);
            }
        }
        __syncthreads();

        if (kt < 15) {
            const float* ksrc = QK + kBase + (long long)((kt + 1) * 64) * 128;
            #pragma unroll
            for (int it = 0; it < 4; it++) {
                int idx = tid + it * 256, r = idx >> 4, c = (idx & 15) << 2;
                cp16(sb + (FK + r * 68 + c) * 4, ksrc + r * 128 + c);
            }
        }
        #pragma unroll
        for (int it = 0; it < 8; it++) {
            int idx = tid + it * 256, r = idx >> 5, c = (idx & 31) << 2;
            cp16(sb + (FV1 + r * 136 + c) * 4, vsrc + 128 + r * 512 + c);
        }
        asm volatile("cp.async.commit_group;" ::: "memory");

        asm volatile("cp.async.wait_group 1;" ::: "memory");
        #pragma unroll
        for (int ks = 0; ks < 8; ks++) {
            uint32_t bf[4][2];
            #pragma unroll
            for (int ni = 0; ni < 4; ni++) {
                int base = FV0 + (ks * 8 + tg) * 136 + wn * 32 + ni * 8 + g;
                bf[ni][0] = __float_as_uint(fs[base]);
                bf[ni][1] = __float_as_uint(fs[base + 4 * 136]);
            }
            #pragma unroll
            for (int mi = 0; mi < 4; mi++) {
                int ab = FE + (wm * 64 + mi * 16 + g) * 68 + ks * 8 + tg;
                uint32_t af[4];
                af[0] = __float_as_uint(fs[ab]);
                af[1] = __float_as_uint(fs[ab + 8 * 68]);
                af[2] = __float_as_uint(fs[ab + 4]);
                af[3] = __float_as_uint(fs[ab + 8 * 68 + 4]);
                #pragma unroll
                for (int ni = 0; ni < 4; ni++)
                    mma_tf32(acc[mi][ni], af, bf[ni]);
            }
        }
        asm volatile("cp.async.wait_group 0;" ::: "memory");
        #pragma unroll
        for (int ks = 0; ks < 8; ks++) {
            uint32_t bf[4][2];
            #pragma unroll
            for (int ni = 0; ni < 4; ni++) {
                int base = FV1 + (ks * 8 + tg) * 136 + wn * 32 + ni * 8 + g;
                bf[ni][0] = __float_as_uint(fs[base]);
                bf[ni][1] = __float_as_uint(fs[base + 4 * 136]);
            }
            #pragma unroll
            for (int mi = 0; mi < 4; mi++) {
                int ab = FE + (wm * 64 + mi * 16 + g) * 68 + ks * 8 + tg;
                uint32_t af[4];
                af[0] = __float_as_uint(fs[ab]);
                af[1] = __float_as_uint(fs[ab + 8 * 68]);
                af[2] = __float_as_uint(fs[ab + 4]);
                af[3] = __float_as_uint(fs[ab + 8 * 68 + 4]);
                #pragma unroll
                for (int ni = 0; ni < 4; ni++)
                    mma_tf32(acc[mi][4 + ni], af, bf[ni]);
            }
        }
    }

    #pragma unroll
    for (int mi = 0; mi < 4; mi++)
        #pragma unroll
        for (int rr = 0; rr < 2; rr++) {
            float v = rs[mi][rr];
            v += __shfl_xor_sync(0xffffffffu, v, 1);
            v += __shfl_xor_sync(0xffffffffu, v, 2);
            if (tg == 0)
                fs[FRS + (wm * 64 + mi * 16 + g + rr * 8) * 4 + wn] = v;
        }
    __syncthreads();
    if (tid < 128)
        fs[FINV + tid] = 1.0f / (fs[FRS + tid * 4] + fs[FRS + tid * 4 + 1] +
                                 fs[FRS + tid * 4 + 2] + fs[FRS + tid * 4 + 3]);
    __syncthreads();

    #pragma unroll
    for (int mi = 0; mi < 4; mi++) {
        #pragma unroll
        for (int rr = 0; rr < 2; rr++) {
            int row = wm * 64 + mi * 16 + g + rr * 8;
            float inv = fs[FINV + row];
            long long mg = (long long)(b * 1024 + mb * 128 + row);
            #pragma unroll
            for (int j = 0; j < 8; j++) {
                int chunk = j >> 2, ni = j & 3;
                int col = h * 512 + half * 256 + chunk * 128 + wn * 32 + ni * 8 + tg * 2;
                float ox = rnd_tf32(acc[mi][j][rr * 2 + 0] * inv);
                float oy = rnd_tf32(acc[mi][j][rr * 2 + 1] * inv);
                *(float2*)(AT + mg * 4096 + col) = make_float2(ox, oy);
            }
        }
    }
}

// ---------------- elementwise kernels ---------------------------------------

__global__ __launch_bounds__(256)
void round_copy(const float4* __restrict__ src, float4* __restrict__ dst, int n4)
{
    int i = blockIdx.x * 256 + threadIdx.x;
    if (i < n4) {
        float4 v = src[i];
        v.x = rnd_tf32(v.x); v.y = rnd_tf32(v.y);
        v.z = rnd_tf32(v.z); v.w = rnd_tf32(v.w);
        dst[i] = v;
    }
}

__global__ __launch_bounds__(256)
void round_concat(const float4* __restrict__ src, float* __restrict__ dst,
                  int n4, int colOff)
{
    int i = blockIdx.x * 256 + threadIdx.x;
    if (i < n4) {
        float4 v = src[i];
        v.x = rnd_tf32(v.x); v.y = rnd_tf32(v.y);
        v.z = rnd_tf32(v.z); v.w = rnd_tf32(v.w);
        int row = i >> 4;
        int c4  = i & 15;
        *(float4*)(dst + (long long)row * 128 + colOff + c4 * 4) = v;
    }
}

__global__ __launch_bounds__(128)
void add_ln512(const float* __restrict__ X, const float* __restrict__ Y,
               const float* __restrict__ gamma, const float* __restrict__ beta,
               float* __restrict__ O, int roundOut)
{
    __shared__ float red[4];
    const long long row = blockIdx.x;
    const int tid = threadIdx.x;

    const float4 x4 = ((const float4*)(X + row * 512))[tid];
    const float4 y4 = ((const float4*)(Y + row * 512))[tid];
    float4 v;
    v.x = x4.x + y4.x; v.y = x4.y + y4.y; v.z = x4.z + y4.z; v.w = x4.w + y4.w;

    float s = (v.x + v.y) + (v.z + v.w);
    #pragma unroll
    for (int o = 16; o > 0; o >>= 1) s += __shfl_xor_sync(0xffffffffu, s, o);
    if ((tid & 31) == 0) red[tid >> 5] = s;
    __syncthreads();
    const float mean = ((red[0] + red[1]) + (red[2] + red[3])) * (1.0f / 512.0f);
    __syncthreads();

    float q = v.x * v.x + v.y * v.y + v.z * v.z + v.w * v.w;
    #pragma unroll
    for (int o = 16; o > 0; o >>= 1) q += __shfl_xor_sync(0xffffffffu, q, o);
    if ((tid & 31) == 0) red[tid >> 5] = q;
    __syncthreads();
    const float var = ((red[0] + red[1]) + (red[2] + red[3])) * (1.0f / 512.0f) - mean * mean;
    const float inv = rsqrtf(var + 1e-3f);

    const int n = tid * 4;
    const float4 g4 = *(const float4*)(gamma + n);
    const float4 b4 = *(const float4*)(beta + n);
    float4 o;
    o.x = g4.x * (v.x - mean) * inv + b4.x;
    o.y = g4.y * (v.y - mean) * inv + b4.y;
    o.z = g4.z * (v.z - mean) * inv + b4.z;
    o.w = g4.w * (v.w - mean) * inv + b4.w;
    if (roundOut) {
        o.x = rnd_tf32(o.x); o.y = rnd_tf32(o.y);
        o.z = rnd_tf32(o.z); o.w = rnd_tf32(o.w);
    }
    ((float4*)(O + row * 512))[tid] = o;
}

// ---------------------------------------------------------------------------

static void run_gemm1(bool tb, const float* A, const float* B, float* C,
                      int M, int N, int K, int lda, int ldb, int ldc,
                      long long sA, long long sB,
                      int zdiv, long long sC1, long long sC2,
                      int batch, float alpha, const float* bias, int relu, int rOut,
                      cudaStream_t st)
{
    dim3 grid((N + BN - 1) / BN, M / BM, batch);
    if (tb)
        tf32_gemm<true><<<grid, 256, SMEM_BYTES, st>>>(A, B, C, M, N, K, lda, ldb, ldc,
            sA, sB, zdiv, sC1, sC2, alpha, bias, relu, rOut);
    else
        tf32_gemm<false><<<grid, 256, SMEM_BYTES, st>>>(A, B, C, M, N, K, lda, ldb, ldc,
            sA, sB, zdiv, sC1, sC2, alpha, bias, relu, rOut);
}

static void run_gemm2(const float* A, const float* B, float* C,
                      int M, int N, int K, int lda, int ldb, int ldc,
                      long long sA, long long sB,
                      int zdiv, long long sC1, long long sC2,
                      int batch, float alpha, const float* bias, int relu, int rOut)
{
    dim3 grid(N / 256, M / 128, batch);
    tf32_gemm2<<<grid, 256, SMEM2>>>(A, B, C, M, N, K, lda, ldb, ldc,
        sA, sB, zdiv, sC1, sC2, alpha, bias, relu, rOut);
}

static void run_round(const float* src, float* dst, int n, cudaStream_t st)
{
    int n4 = n / 4;
    round_copy<<<(n4 + 255) / 256, 256, 0, st>>>((const float4*)src, (float4*)dst, n4);
}

struct Ptrs {
    float *qk, *v, *at, *mha, *h, *f1, *f2;
    float *xr, *qkw, *vwr, *lwr, *w1r, *w2r;
    cudaStream_t s2;
    cudaEvent_t evFork, evFork2, evJoin;
};

static Ptrs get_ptrs()
{
    static Ptrs p;
    static bool init = false;
    if (!init) {
        cudaGetSymbolAddress((void**)&p.qk,  g_qk);
        cudaGetSymbolAddress((void**)&p.v,   g_v);
        cudaGetSymbolAddress((void**)&p.at,  g_at);
        cudaGetSymbolAddress((void**)&p.mha, g_mha);
        cudaGetSymbolAddress((void**)&p.h,   g_h);
        cudaGetSymbolAddress((void**)&p.f1,  g_f1);
        cudaGetSymbolAddress((void**)&p.f2,  g_f2);
        cudaGetSymbolAddress((void**)&p.xr,  g_xr);
        cudaGetSymbolAddress((void**)&p.qkw, g_qkw);
        cudaGetSymbolAddress((void**)&p.vwr, g_vwr);
        cudaGetSymbolAddress((void**)&p.lwr, g_lwr);
        cudaGetSymbolAddress((void**)&p.w1r, g_w1r);
        cudaGetSymbolAddress((void**)&p.w2r, g_w2r);
        cudaFuncSetAttribute(tf32_gemm<true>,  cudaFuncAttributeMaxDynamicSharedMemorySize, SMEM_BYTES);
        cudaFuncSetAttribute(tf32_gemm<false>, cudaFuncAttributeMaxDynamicSharedMemorySize, SMEM_BYTES);
        cudaFuncSetAttribute(tf32_gemm2,       cudaFuncAttributeMaxDynamicSharedMemorySize, SMEM2);
        cudaFuncSetAttribute(flash_attn,       cudaFuncAttributeMaxDynamicSharedMemorySize, FLASH_SMEM);
        cudaStreamCreateWithFlags(&p.s2, cudaStreamNonBlocking);
        cudaEventCreateWithFlags(&p.evFork,  cudaEventDisableTiming);
        cudaEventCreateWithFlags(&p.evFork2, cudaEventDisableTiming);
        cudaEventCreateWithFlags(&p.evJoin,  cudaEventDisableTiming);
        init = true;
    }
    return p;
}

extern "C" void kernel_launch(void* const* d_in, const int* in_sizes, int n_in,
                              void* d_out, int out_size)
{
    const float* x      = (const float*)d_in[0];   // [8,1024,512]
    const float* qw     = (const float*)d_in[1];   // [8,512,64]
    const float* kw     = (const float*)d_in[2];   // [8,512,64]
    const float* vw     = (const float*)d_in[3];   // [8,512,512]
    const float* lw     = (const float*)d_in[4];   // [4096,512]
    const float* gamma1 = (const float*)d_in[5];
    const float* beta1  = (const float*)d_in[6];
    const float* w1     = (const float*)d_in[7];   // [512,2048]
    const float* b1     = (const float*)d_in[8];
    const float* w2     = (const float*)d_in[9];   // [2048,512]
    const float* b2     = (const float*)d_in[10];
    const float* gamma2 = (const float*)d_in[11];
    const float* beta2  = (const float*)d_in[12];
    float* out = (float*)d_out;

    Ptrs p = get_ptrs();
    const int M = 8192;
    const float scale = 0.044194173824159216f;  // 1/sqrt(512)

    // ---- fork side stream (weight rounds + QK proj run concurrently) ----
    cudaEventRecord(p.evFork, 0);
    cudaStreamWaitEvent(p.s2, p.evFork, 0);

    // side stream: rounds that nothing upstream depends on
    round_concat<<<(65536 + 255) / 256, 256, 0, p.s2>>>((const float4*)qw, p.qkw, 65536, 0);
    round_concat<<<(65536 + 255) / 256, 256, 0, p.s2>>>((const float4*)kw, p.qkw, 65536, 64);
    run_round(lw, p.lwr, 2097152, p.s2);
    run_round(w1, p.w1r, 1048576, p.s2);
    run_round(w2, p.w2r, 1048576, p.s2);

    // main stream: x + vw rounds
    run_round(x,  p.xr,  4194304, 0);
    run_round(vw, p.vwr, 2097152, 0);

    // s2 additionally needs xr for QK proj: fork again after x round
    cudaEventRecord(p.evFork2, 0);
    cudaStreamWaitEvent(p.s2, p.evFork2, 0);

    // QK = x @ [qw|kw][h] -> [H][8192][128] (rounded out)   [side stream]
    run_gemm1(false, p.xr, p.qkw, p.qk, M, 128, 512, 512, 128, 128,
              0LL, 65536LL, 1, 1048576LL, 0LL, 8, 1.0f, nullptr, 0, 1, p.s2);

    // V = x @ vw[h] -> [H][8192][512] (rounded out)         [main stream]
    run_gemm2(p.xr, p.vwr, p.v, M, 512, 512, 512, 512, 512,
              0LL, 262144LL, 1, 4194304LL, 0LL, 8, 1.0f, nullptr, 0, 1);

    // ---- join: flash needs QK (s2) and V (main) ----
    cudaEventRecord(p.evJoin, p.s2);
    cudaStreamWaitEvent(0, p.evJoin, 0);

    // fused attention: softmax(scale * Q K^T) @ V -> g_at (concat, rounded)
    flash_attn<<<dim3(2, 8, 64), 256, FLASH_SMEM>>>(p.qk, p.v, p.at, scale);

    // mha = attn @ lw (fp32)
    run_gemm2(p.at, p.lwr, p.mha, M, 512, 4096, 4096, 512, 512,
              0LL, 0LL, 1, 0LL, 0LL, 1, 1.0f, nullptr, 0, 0);

    // h = LN(x + mha)  (rounded: feeds FFN1)
    add_ln512<<<8192, 128>>>(x, p.mha, gamma1, beta1, p.h, 1);

    // f1 = relu(h @ w1 + b1) (rounded out)
    run_gemm2(p.h, p.w1r, p.f1, M, 2048, 512, 512, 2048, 2048,
              0LL, 0LL, 1, 0LL, 0LL, 1, 1.0f, b1, 1, 1);
    // f2 = f1 @ w2 + b2 (fp32)
    run_gemm2(p.f1, p.w2r, p.f2, M, 512, 2048, 2048, 512, 512,
              0LL, 0LL, 1, 0LL, 0LL, 1, 1.0f, b2, 0, 0);

    // out = LN(h + f2)
    add_ln512<<<8192, 128>>>(p.h, p.f2, gamma2, beta2, out, 0);
}